// round 9
// baseline (speedup 1.0000x reference)
#include <cuda_runtime.h>
#include <math.h>

#define HW    80
#define NPIX  6400          // 80*80
#define NPAIR 32            // B*L*L
#define NIMG  8             // B*L

typedef unsigned long long ull;

// ---------------- scratch (static __device__, no allocations) ----------------
__device__ float g_minv[NPAIR * 6];
__device__ float g_mask[NPAIR * NPIX];
__device__ float g_masksum[NIMG * NPIX];
__device__ float g_y[NIMG * 64 * NPIX];        // ping
__device__ float g_y2[NIMG * 64 * NPIX];       // pong
__device__ float g_convn[NPAIR * 64 * NPIX];   // conv(neighbor)
__device__ float g_ego[NIMG * 64 * NPIX];      // conv(ego)+bias
__device__ float2 g_wnbr2[32 * 64 * 9];        // [co2][cin][tap] cout-paired
__device__ float2 g_wego2[32 * 64 * 9];
__device__ float2 g_wgru2[64 * 128 * 9];       // [(upd,cand) pair][ci][tap]
__device__ float2 g_bgru2[64];                 // (gates_b[64+j], can_b[j])

// ---------------- packed fp32x2 helpers (sm_103a FFMA2) ----------------
__device__ __forceinline__ void fma2(ull& d, ull a, ull b) {
    asm("fma.rn.f32x2 %0, %1, %2, %0;" : "+l"(d) : "l"(a), "l"(b));
}
__device__ __forceinline__ ull bcast2(float v) {
    ull r;
    asm("mov.b64 %0, {%1, %1};" : "=l"(r) : "f"(v));
    return r;
}
__device__ __forceinline__ float2 unpack2(ull v) {
    float2 f;
    asm("mov.b64 {%0, %1}, %2;" : "=f"(f.x), "=f"(f.y) : "l"(v));
    return f;
}
__device__ __forceinline__ void lds_v2u64(ull& a, ull& b, const ull* p) {
    asm("ld.shared.v2.u64 {%0, %1}, [%2];"
        : "=l"(a), "=l"(b) : "l"(__cvta_generic_to_shared(p)));
}

// accurate activations (avoid fast-math tanh.approx)
__device__ __forceinline__ float sigmoid_acc(float u) {
    return 1.0f / (1.0f + expf(-u));
}
__device__ __forceinline__ float tanh_acc(float x) {
    float a = fabsf(x);
    float e = expf(-2.0f * a);
    float t = (1.0f - e) / (1.0f + e);
    return copysignf(t, x);
}

// ---------------- affine inverse: replicate reference fp32 arithmetic -------
__global__ void k_minv(const float* __restrict__ P) {
    int p = threadIdx.x;
    if (p >= NPAIR) return;
    const float* M = P + p * 16;
    float a = M[0], b = M[1];
    float c = M[4], d = M[5];
    float txs = __fdiv_rn(M[3], 0.8f);
    float tys = __fdiv_rn(M[7], 0.8f);
    const float cx = 40.0f, cy = 40.0f;
    float dot0 = __fadd_rn(__fmul_rn(a, cx), __fmul_rn(b, cy));
    float dot1 = __fadd_rn(__fmul_rn(c, cx), __fmul_rn(d, cy));
    float Tx = __fadd_rn(__fsub_rn(cx, dot0), txs);
    float Ty = __fadd_rn(__fsub_rn(cy, dot1), tys);

    float ra  = __fdiv_rn(1.0f, a);
    float l10 = __fmul_rn(c, ra);
    float u22 = __fmaf_rn(-l10, b, d);
    float u23 = __fmaf_rn(-l10, Tx, Ty);

    float x1_0 = __fdiv_rn(-l10, u22);
    float x0_0 = __fdiv_rn(__fmaf_rn(-b, x1_0, 1.0f), a);
    float x1_1 = __fdiv_rn(1.0f, u22);
    float x0_1 = __fdiv_rn(__fmul_rn(-b, x1_1), a);
    float x1_2 = __fdiv_rn(-u23, u22);
    float x0_2 = __fdiv_rn(__fmaf_rn(-b, x1_2, -Tx), a);

    float* o = g_minv + p * 6;
    o[0] = x0_0; o[1] = x0_1; o[2] = x0_2;
    o[3] = x1_0; o[4] = x1_1; o[5] = x1_2;
}

__device__ __forceinline__ float coordx(const float* mv, float x, float y) {
    float s = __fmul_rn(mv[0], x);
    s = __fmaf_rn(mv[1], y, s);
    return __fadd_rn(s, mv[2]);
}
__device__ __forceinline__ float coordy(const float* mv, float x, float y) {
    float s = __fmul_rn(mv[3], x);
    s = __fmaf_rn(mv[4], y, s);
    return __fadd_rn(s, mv[5]);
}

// ---------------- masks + masksum fused ----------------
__global__ void k_maskall() {
    int bj = blockIdx.y;                 // b*4 + j
    int p = blockIdx.x * 256 + threadIdx.x;
    if (p >= NPIX) return;
    int b = bj >> 2, j = bj & 3;
    float x = (float)(p % HW), y = (float)(p / HW);
    float s = 0.0f;
#pragma unroll
    for (int i = 0; i < 4; i++) {
        int pair = (b * 4 + i) * 4 + j;
        const float* mv = g_minv + pair * 6;
        float sx = coordx(mv, x, y);
        float sy = coordy(mv, x, y);
        int ix = (int)rintf(sx);
        int iy = (int)rintf(sy);
        float m = (ix >= 0 && ix < HW && iy >= 0 && iy < HW) ? 1.0f : 0.0f;
        g_mask[pair * NPIX + p] = m;
        s += m;
    }
    g_masksum[bj * NPIX + p] = s;
}

// ---------------- initial transform: y[c,h,w] = x[c, 79-w, h] ----------------
__global__ void k_transform(const float* __restrict__ x) {
    int idx = blockIdx.x * 256 + threadIdx.x;
    int p = idx % NPIX;
    int c = (idx / NPIX) & 63;
    int bl = idx / (NPIX * 64);
    int h = p / HW, w = p % HW;
    g_y[idx] = x[(bl * 64 + c) * NPIX + (HW - 1 - w) * HW + h];
}

// ======== fused tiled direct 3x3 conv (SAME), NCHW fp32, FFMA2 ========
// 16x16 tile, 256 thr: 4 cout-groups (8 pairs) x 64 px-groups (4 px each).
// Pixel tile stored DUPLICATED as f32x2 (ull) -> inner pixel op is one LDS.64.
// Weights padded to stride 10 -> ld.shared.v2.u64.
// MODE 0: z<32 -> NBR (bilinear-warp staging, mask skip) ; z>=32 -> EGO(+msg_b)
// MODE 2: GRU (ci<64 y, ci>=64 masked-mean agg on the fly; (upd,cand) lanes;
//         epilogue sigmoid*tanh -> ydst)
// dyn smem layout (ull units): sXd[8*18*20]=2880 | sW[32*80]=2560 | aux 1296
#define SMX 0
#define SMW 2880
#define SMA 5440
#define SM_ULL (5440 + 1296)

template <int MODE, int CIN>
__global__ __launch_bounds__(256, 2)
void conv_all(const float* __restrict__ ysrc,
              const float* __restrict__ convn,
              const float* __restrict__ ego,
              const float2* __restrict__ Wnbr,
              const float2* __restrict__ Wego,
              const float* __restrict__ msgb,
              const float2* __restrict__ bgru2,
              float* __restrict__ convn_out,
              float* __restrict__ ego_out,
              float* __restrict__ ydst) {
    extern __shared__ ull smd[];
    ull* sXd = smd + SMX;                 // [ci][row 18][col pad20]
    ull* sW  = smd + SMW;                 // [pair 32][ci 8][tap pad10]
    float4* aw  = (float4*)(smd + SMA);   // MODE0: 324 float4
    int4*   aiv = (int4*)(smd + SMA + 648);
    float*  amk = (float*)(smd + SMA);    // MODE2: 324*5 floats

    const int z = blockIdx.z;
    const bool isNbr = (MODE == 0) && (z < 32);
    const int img = (MODE == 0) ? (isNbr ? z : z - 32) : z;
    const int tx = blockIdx.x % 5, ty = blockIdx.x / 5;
    const int w0 = tx * 16, h0 = ty * 16;
    const int t = threadIdx.x;
    const int s = t & 63;
    const int wl = s & 15;
    const int hq = s >> 4;
    const int cg = t >> 6;

    const float* srcI = nullptr;
    const float2* Wt2;
    if (MODE == 0) {
        if (isNbr) {
            const float* mp = g_mask + (long)img * NPIX;
            int any = 0;
#pragma unroll
            for (int k = 0; k < 4; k++)
                any |= (mp[(h0 + hq * 4 + k) * HW + (w0 + wl)] != 0.0f);
            if (__syncthreads_count(any) == 0) return;
            int b = img >> 4, i = (img >> 2) & 3;
            srcI = ysrc + (long)(b * 4 + i) * 64 * NPIX;
            const float* mv = g_minv + img * 6;
            for (int idx = t; idx < 324; idx += 256) {
                int r = idx / 18, c = idx % 18;
                int gh = h0 - 1 + r, gw = w0 - 1 + c;
                float4 wv = make_float4(0.f, 0.f, 0.f, 0.f);
                int4 iv = make_int4(0, 0, 0, 0);
                if (gh >= 0 && gh < HW && gw >= 0 && gw < HW) {
                    float X = (float)gw, Y = (float)gh;
                    float sx = coordx(mv, X, Y);
                    float sy = coordy(mv, X, Y);
                    float x0f = floorf(sx), y0f = floorf(sy);
                    float fx = __fsub_rn(sx, x0f), fy = __fsub_rn(sy, y0f);
                    int x0 = (int)x0f, y0 = (int)y0f;
                    int x1 = x0 + 1, y1 = y0 + 1;
                    int cx0 = min(max(x0, 0), HW - 1), cx1 = min(max(x1, 0), HW - 1);
                    int cy0 = min(max(y0, 0), HW - 1), cy1 = min(max(y1, 0), HW - 1);
                    float vx0 = (x0 >= 0 && x0 < HW) ? 1.0f : 0.0f;
                    float vx1 = (x1 >= 0 && x1 < HW) ? 1.0f : 0.0f;
                    float vy0 = (y0 >= 0 && y0 < HW) ? 1.0f : 0.0f;
                    float vy1 = (y1 >= 0 && y1 < HW) ? 1.0f : 0.0f;
                    float gx = __fsub_rn(1.0f, fx), gy = __fsub_rn(1.0f, fy);
                    wv.x = __fmul_rn(__fmul_rn(vx0, vy0), __fmul_rn(gx, gy));
                    wv.y = __fmul_rn(__fmul_rn(vx1, vy0), __fmul_rn(fx, gy));
                    wv.z = __fmul_rn(__fmul_rn(vx0, vy1), __fmul_rn(gx, fy));
                    wv.w = __fmul_rn(__fmul_rn(vx1, vy1), __fmul_rn(fx, fy));
                    iv.x = cy0 * HW + cx0; iv.y = cy0 * HW + cx1;
                    iv.z = cy1 * HW + cx0; iv.w = cy1 * HW + cx1;
                }
                aw[idx] = wv;
                aiv[idx] = iv;
            }
            __syncthreads();
            Wt2 = Wnbr;
        } else {
            srcI = ysrc + (long)img * 64 * NPIX;
            Wt2 = Wego;
        }
    } else {
        srcI = ysrc + (long)img * 64 * NPIX;
        Wt2 = Wnbr;                  // carries gru weights in MODE2 call
        int b = img >> 2, j = img & 3;
        for (int idx = t; idx < 324; idx += 256) {
            int r = idx / 18, c = idx % 18;
            int gh = h0 - 1 + r, gw = w0 - 1 + c;
            float ms = 0.f, m0 = 0.f, m1 = 0.f, m2 = 0.f, m3 = 0.f;
            if (gh >= 0 && gh < HW && gw >= 0 && gw < HW) {
                int p = gh * HW + gw;
                ms = g_masksum[img * NPIX + p];
                m0 = g_mask[((b * 4 + 0) * 4 + j) * NPIX + p];
                m1 = g_mask[((b * 4 + 1) * 4 + j) * NPIX + p];
                m2 = g_mask[((b * 4 + 2) * 4 + j) * NPIX + p];
                m3 = g_mask[((b * 4 + 3) * 4 + j) * NPIX + p];
            }
            amk[idx * 5 + 0] = ms; amk[idx * 5 + 1] = m0;
            amk[idx * 5 + 2] = m1; amk[idx * 5 + 3] = m2;
            amk[idx * 5 + 4] = m3;
        }
        __syncthreads();
    }

    ull acc2[4][8];
#pragma unroll
    for (int k = 0; k < 4; k++)
#pragma unroll
        for (int j = 0; j < 8; j++) acc2[k][j] = 0ULL;

    for (int cin0 = 0; cin0 < CIN; cin0 += 8) {
        // ---- stage input (duplicated f32x2): 8ci x 18 x 18 ----
        for (int idx = t; idx < 8 * 324; idx += 256) {
            int ci = idx / 324, rem = idx % 324;
            int r = rem / 18, c = rem % 18;
            float v = 0.0f;
            if (MODE == 0 && isNbr) {
                float4 wv = aw[rem];
                int4 iv = aiv[rem];
                const float* sc = srcI + (cin0 + ci) * NPIX;
                v = __fmul_rn(wv.x, sc[iv.x]);
                v = __fadd_rn(v, __fmul_rn(wv.y, sc[iv.y]));
                v = __fadd_rn(v, __fmul_rn(wv.z, sc[iv.z]));
                v = __fadd_rn(v, __fmul_rn(wv.w, sc[iv.w]));
            } else {
                int gh = h0 - 1 + r, gw = w0 - 1 + c;
                if (gh >= 0 && gh < HW && gw >= 0 && gw < HW) {
                    int p = gh * HW + gw;
                    if (MODE == 0 || cin0 < 64) {
                        v = srcI[(cin0 + ci) * NPIX + p];
                    } else {
                        int cb = cin0 - 64 + ci;
                        int b = img >> 2, j = img & 3;
                        v = __fmul_rn(amk[rem * 5 + 0],
                                      ego[((long)img * 64 + cb) * NPIX + p]);
                        v = __fmaf_rn(amk[rem * 5 + 1],
                                      convn[((long)((b * 4 + 0) * 4 + j) * 64 + cb) * NPIX + p], v);
                        v = __fmaf_rn(amk[rem * 5 + 2],
                                      convn[((long)((b * 4 + 1) * 4 + j) * 64 + cb) * NPIX + p], v);
                        v = __fmaf_rn(amk[rem * 5 + 3],
                                      convn[((long)((b * 4 + 2) * 4 + j) * 64 + cb) * NPIX + p], v);
                        v = __fmaf_rn(amk[rem * 5 + 4],
                                      convn[((long)((b * 4 + 3) * 4 + j) * 64 + cb) * NPIX + p], v);
                        v = __fmul_rn(0.25f, v);
                    }
                }
            }
            sXd[ci * 360 + r * 20 + c] = bcast2(v);
        }
        // ---- stage weights: 32 pairs x 8ci x 9 -> padded stride 10 ----
        for (int idx = t; idx < 32 * 72; idx += 256) {
            int co2 = idx / 72, rem = idx % 72;
            int ci = rem / 9, tap = rem % 9;
            float2 wv = Wt2[((blockIdx.y * 32 + co2) * CIN + cin0 + ci) * 9 + tap];
            sW[co2 * 80 + ci * 10 + tap] = *reinterpret_cast<ull*>(&wv);
        }
        __syncthreads();
#pragma unroll 1
        for (int ci = 0; ci < 8; ci++) {
            ull xr[6][3];
            const ull* xp = &sXd[ci * 360 + (hq * 4) * 20 + wl];
#pragma unroll
            for (int rr = 0; rr < 6; rr++)
#pragma unroll
                for (int cc = 0; cc < 3; cc++)
                    xr[rr][cc] = xp[rr * 20 + cc];
            const ull* wp = &sW[(cg * 8) * 80 + ci * 10];
#pragma unroll
            for (int j = 0; j < 8; j++) {
                ull w[9];
                lds_v2u64(w[0], w[1], wp + j * 80 + 0);
                lds_v2u64(w[2], w[3], wp + j * 80 + 2);
                lds_v2u64(w[4], w[5], wp + j * 80 + 4);
                lds_v2u64(w[6], w[7], wp + j * 80 + 6);
                w[8] = wp[j * 80 + 8];
#pragma unroll
                for (int tap = 0; tap < 9; tap++) {
                    int r = tap / 3, c = tap % 3;
                    fma2(acc2[0][j], xr[0 + r][c], w[tap]);
                    fma2(acc2[1][j], xr[1 + r][c], w[tap]);
                    fma2(acc2[2][j], xr[2 + r][c], w[tap]);
                    fma2(acc2[3][j], xr[3 + r][c], w[tap]);
                }
            }
        }
        __syncthreads();
    }
    // ---- epilogue ----
    if (MODE == 2) {
#pragma unroll
        for (int j = 0; j < 8; j++) {
            int pr = blockIdx.y * 32 + cg * 8 + j;
            float2 bb = bgru2[pr];
#pragma unroll
            for (int k = 0; k < 4; k++) {
                int h = h0 + hq * 4 + k, w = w0 + wl;
                float2 f = unpack2(acc2[k][j]);
                ydst[((long)img * 64 + pr) * NPIX + h * HW + w] =
                    sigmoid_acc(f.x + bb.x) * tanh_acc(f.y + bb.y);
            }
        }
    } else {
        float* outp = isNbr ? (convn_out + (long)img * 64 * NPIX)
                            : (ego_out + (long)img * 64 * NPIX);
#pragma unroll
        for (int j = 0; j < 8; j++) {
            int co = (cg * 8 + j) * 2;
            float bv0 = isNbr ? 0.0f : msgb[co];
            float bv1 = isNbr ? 0.0f : msgb[co + 1];
#pragma unroll
            for (int k = 0; k < 4; k++) {
                int h = h0 + hq * 4 + k, w = w0 + wl;
                float2 f = unpack2(acc2[k][j]);
                outp[(long)co * NPIX + h * HW + w] = f.x + bv0;
                outp[(long)(co + 1) * NPIX + h * HW + w] = f.y + bv1;
            }
        }
    }
}

// ---------------- weight prepack ----------------
__global__ void k_prepack(const float* __restrict__ msg_w,
                          const float* __restrict__ gates_w,
                          const float* __restrict__ gates_b,
                          const float* __restrict__ can_w,
                          const float* __restrict__ can_b) {
    int idx = blockIdx.x * 256 + threadIdx.x;
    if (idx < 18432) {                         // msg split: [co2][ci<64][9]
        int co2 = idx / 576, rem = idx % 576;
        int coA = 2 * co2, coB = 2 * co2 + 1;
        g_wnbr2[idx] = make_float2(msg_w[coA * 1152 + rem],
                                   msg_w[coB * 1152 + rem]);
        g_wego2[idx] = make_float2(msg_w[coA * 1152 + 576 + rem],
                                   msg_w[coB * 1152 + 576 + rem]);
        return;
    }
    int k = idx - 18432;
    if (k < 73728) {                           // gru (update,cand) lane pairs
        int pr = k / 1152, rem = k % 1152;
        g_wgru2[k] = make_float2(gates_w[(64 + pr) * 1728 + rem],
                                 can_w[pr * 1728 + rem]);
        return;
    }
    k -= 73728;
    if (k < 64)
        g_bgru2[k] = make_float2(gates_b[64 + k], can_b[k]);
}

// ---------------- output: out[b,h,w,o] = mlp_w[o,:]·h1[b,0,:,w,79-h]+mlp_b ----
__global__ void k_out(const float* __restrict__ mlp_w,
                      const float* __restrict__ mlp_b,
                      const float* __restrict__ yfin,
                      float* __restrict__ out) {
    __shared__ float sW[64 * 65];
    __shared__ float sx[4][64];
    int t = threadIdx.x;
    for (int idx = t; idx < 4096; idx += 256) {
        int o = idx >> 6, c = idx & 63;
        sW[c * 65 + o] = mlp_w[idx];
    }
    int pix = t >> 6, o = t & 63;
    int pp = blockIdx.x * 4 + pix;
    int b = pp / NPIX, pr = pp % NPIX;
    int h = pr / HW, w = pr % HW;
    int q = w * HW + (HW - 1 - h);
    sx[pix][o] = yfin[(b * 4) * 64 * NPIX + o * NPIX + q];
    __syncthreads();
    float acc = mlp_b[o];
#pragma unroll 8
    for (int c = 0; c < 64; c++)
        acc = fmaf(sx[pix][c], sW[c * 65 + o], acc);
    out[pp * 64 + o] = acc;
}

// ---------------- host orchestration ----------------
extern "C" void kernel_launch(void* const* d_in, const int* in_sizes, int n_in,
                              void* d_out, int out_size) {
    const float* x       = (const float*)d_in[0];
    const float* pt      = (const float*)d_in[2];
    const float* msg_w   = (const float*)d_in[4];
    const float* msg_b   = (const float*)d_in[5];
    const float* gates_w = (const float*)d_in[6];
    const float* gates_b = (const float*)d_in[7];
    const float* can_w   = (const float*)d_in[8];
    const float* can_b   = (const float*)d_in[9];
    const float* mlp_w   = (const float*)d_in[10];
    const float* mlp_b   = (const float*)d_in[11];

    float *p_y, *p_y2, *p_convn, *p_ego;
    float2 *p_wnbr2, *p_wego2, *p_wgru2, *p_bgru2;
    cudaGetSymbolAddress((void**)&p_y, g_y);
    cudaGetSymbolAddress((void**)&p_y2, g_y2);
    cudaGetSymbolAddress((void**)&p_convn, g_convn);
    cudaGetSymbolAddress((void**)&p_ego, g_ego);
    cudaGetSymbolAddress((void**)&p_wnbr2, g_wnbr2);
    cudaGetSymbolAddress((void**)&p_wego2, g_wego2);
    cudaGetSymbolAddress((void**)&p_wgru2, g_wgru2);
    cudaGetSymbolAddress((void**)&p_bgru2, g_bgru2);

    const int smemB = SM_ULL * 8;        // 53888 B dynamic shared
    cudaFuncSetAttribute(conv_all<0, 64>,
                         cudaFuncAttributeMaxDynamicSharedMemorySize, smemB);
    cudaFuncSetAttribute(conv_all<2, 128>,
                         cudaFuncAttributeMaxDynamicSharedMemorySize, smemB);

    k_minv<<<1, 32>>>(pt);
    k_prepack<<<(18432 + 73728 + 64 + 255) / 256, 256>>>(msg_w, gates_w,
                                                         gates_b, can_w, can_b);
    k_maskall<<<dim3(25, NIMG), 256>>>();
    k_transform<<<(NIMG * 64 * NPIX) / 256, 256>>>(x);

    for (int it = 0; it < 2; it++) {
        const float* ysrc = (it == 0) ? p_y : p_y2;
        float* ydst       = (it == 0) ? p_y2 : p_y;
        // merged NBR(32 pairs) + EGO(8 imgs): one launch, 1000 blocks
        conv_all<0, 64><<<dim3(25, 1, 40), 256, smemB>>>(
            ysrc, nullptr, nullptr, p_wnbr2, p_wego2, msg_b, nullptr,
            p_convn, p_ego, nullptr);
        // GRU conv with fused agg + pointwise: 400 blocks
        conv_all<2, 128><<<dim3(25, 2, NIMG), 256, smemB>>>(
            ysrc, p_convn, p_ego, p_wgru2, nullptr, nullptr, p_bgru2,
            nullptr, nullptr, ydst);
    }

    k_out<<<2 * NPIX / 4, 256>>>(mlp_w, mlp_b, p_y, (float*)d_out);
}

// round 10
// speedup vs baseline: 1.2498x; 1.2498x over previous
#include <cuda_runtime.h>
#include <math.h>

#define HW    80
#define NPIX  6400          // 80*80
#define NPAIR 32            // B*L*L
#define NIMG  8             // B*L

typedef unsigned long long ull;

// ---------------- scratch (static __device__, no allocations) ----------------
__device__ float g_minv[NPAIR * 6];
__device__ float g_mask[NPAIR * NPIX];
__device__ float g_masksum[NIMG * NPIX];
__device__ float g_y[NIMG * 64 * NPIX];        // ping
__device__ float g_y2[NIMG * 64 * NPIX];       // pong
__device__ float g_convn[NPAIR * 64 * NPIX];   // conv(neighbor)
__device__ float g_ego[NIMG * 64 * NPIX];      // conv(ego)+bias
__device__ float2 g_wnbr2[32 * 64 * 9];        // [co2][cin][tap] cout-paired
__device__ float2 g_wego2[32 * 64 * 9];
__device__ float2 g_wgru2[64 * 128 * 9];       // [(upd,cand) pair][ci][tap]
__device__ float2 g_bgru2[64];                 // (gates_b[64+j], can_b[j])

// ---------------- packed fp32x2 helpers (sm_103a FFMA2) ----------------
__device__ __forceinline__ void fma2(ull& d, ull a, ull b) {
    asm("fma.rn.f32x2 %0, %1, %2, %0;" : "+l"(d) : "l"(a), "l"(b));
}
__device__ __forceinline__ ull bcast2(float v) {
    ull r;
    asm("mov.b64 %0, {%1, %1};" : "=l"(r) : "f"(v));
    return r;
}
__device__ __forceinline__ float2 unpack2(ull v) {
    float2 f;
    asm("mov.b64 {%0, %1}, %2;" : "=f"(f.x), "=f"(f.y) : "l"(v));
    return f;
}

// accurate activations (avoid fast-math tanh.approx)
__device__ __forceinline__ float sigmoid_acc(float u) {
    return 1.0f / (1.0f + expf(-u));
}
__device__ __forceinline__ float tanh_acc(float x) {
    float a = fabsf(x);
    float e = expf(-2.0f * a);
    float t = (1.0f - e) / (1.0f + e);
    return copysignf(t, x);
}

// ---------------- affine inverse: replicate reference fp32 arithmetic -------
__global__ void k_minv(const float* __restrict__ P) {
    int p = threadIdx.x;
    if (p >= NPAIR) return;
    const float* M = P + p * 16;
    float a = M[0], b = M[1];
    float c = M[4], d = M[5];
    float txs = __fdiv_rn(M[3], 0.8f);
    float tys = __fdiv_rn(M[7], 0.8f);
    const float cx = 40.0f, cy = 40.0f;
    float dot0 = __fadd_rn(__fmul_rn(a, cx), __fmul_rn(b, cy));
    float dot1 = __fadd_rn(__fmul_rn(c, cx), __fmul_rn(d, cy));
    float Tx = __fadd_rn(__fsub_rn(cx, dot0), txs);
    float Ty = __fadd_rn(__fsub_rn(cy, dot1), tys);

    float ra  = __fdiv_rn(1.0f, a);
    float l10 = __fmul_rn(c, ra);
    float u22 = __fmaf_rn(-l10, b, d);
    float u23 = __fmaf_rn(-l10, Tx, Ty);

    float x1_0 = __fdiv_rn(-l10, u22);
    float x0_0 = __fdiv_rn(__fmaf_rn(-b, x1_0, 1.0f), a);
    float x1_1 = __fdiv_rn(1.0f, u22);
    float x0_1 = __fdiv_rn(__fmul_rn(-b, x1_1), a);
    float x1_2 = __fdiv_rn(-u23, u22);
    float x0_2 = __fdiv_rn(__fmaf_rn(-b, x1_2, -Tx), a);

    float* o = g_minv + p * 6;
    o[0] = x0_0; o[1] = x0_1; o[2] = x0_2;
    o[3] = x1_0; o[4] = x1_1; o[5] = x1_2;
}

__device__ __forceinline__ float coordx(const float* mv, float x, float y) {
    float s = __fmul_rn(mv[0], x);
    s = __fmaf_rn(mv[1], y, s);
    return __fadd_rn(s, mv[2]);
}
__device__ __forceinline__ float coordy(const float* mv, float x, float y) {
    float s = __fmul_rn(mv[3], x);
    s = __fmaf_rn(mv[4], y, s);
    return __fadd_rn(s, mv[5]);
}

// ---------------- masks + masksum fused ----------------
__global__ void k_maskall() {
    int bj = blockIdx.y;                 // b*4 + j
    int p = blockIdx.x * 256 + threadIdx.x;
    if (p >= NPIX) return;
    int b = bj >> 2, j = bj & 3;
    float x = (float)(p % HW), y = (float)(p / HW);
    float s = 0.0f;
#pragma unroll
    for (int i = 0; i < 4; i++) {
        int pair = (b * 4 + i) * 4 + j;
        const float* mv = g_minv + pair * 6;
        float sx = coordx(mv, x, y);
        float sy = coordy(mv, x, y);
        int ix = (int)rintf(sx);
        int iy = (int)rintf(sy);
        float m = (ix >= 0 && ix < HW && iy >= 0 && iy < HW) ? 1.0f : 0.0f;
        g_mask[pair * NPIX + p] = m;
        s += m;
    }
    g_masksum[bj * NPIX + p] = s;
}

// ---------------- initial transform: y[c,h,w] = x[c, 79-w, h] ----------------
__global__ void k_transform(const float* __restrict__ x) {
    int idx = blockIdx.x * 256 + threadIdx.x;
    int p = idx % NPIX;
    int c = (idx / NPIX) & 63;
    int bl = idx / (NPIX * 64);
    int h = p / HW, w = p % HW;
    g_y[idx] = x[(bl * 64 + c) * NPIX + (HW - 1 - w) * HW + h];
}

// ======== fused tiled direct 3x3 conv (SAME), NCHW fp32, FFMA2 ========
// 16x8 tile, 128 thr: 4 cout-groups (8 pairs) x 32 px-groups (4 px each).
// Per-thread inner loop identical to the best (R7) kernel: 288 FFMA2 per
// ci-slice vs ~108 other inst. 4 blocks/SM (staggered phases) hide staging.
// MODE 0: z<32 -> NBR (bilinear-warp staging, mask skip) ; z>=32 -> EGO(+msg_b)
// MODE 2: GRU (ci<64 y, ci>=64 masked-mean agg on the fly; (upd,cand) lanes;
//         epilogue sigmoid*tanh -> ydst)
template <int MODE, int CIN>
__global__ __launch_bounds__(128, 4)
void conv_all(const float* __restrict__ ysrc,
              const float* __restrict__ convn,
              const float* __restrict__ ego,
              const float2* __restrict__ Wnbr,
              const float2* __restrict__ Wego,
              const float* __restrict__ msgb,
              const float2* __restrict__ bgru2,
              float* __restrict__ convn_out,
              float* __restrict__ ego_out,
              float* __restrict__ ydst) {
    __shared__ float sX[8][10][20];          // 8ci x 10 halo rows x 18(+2)
    __shared__ float2 sW2[32 * 72];          // 32 pairs x 8 ci x 9 taps
    __shared__ union {
        struct { float4 w[180]; int4 iv[180]; } nbr;
        struct { float mk[180][5]; } gru;
    } aux;

    const int z = blockIdx.z;
    const bool isNbr = (MODE == 0) && (z < 32);
    const int img = (MODE == 0) ? (isNbr ? z : z - 32) : z;
    const int tx = blockIdx.x % 5, ty = blockIdx.x / 5;
    const int w0 = tx * 16, h0 = ty * 8;
    const int t = threadIdx.x;
    const int s = t & 31;
    const int wl = s & 15;           // col in tile
    const int hq = s >> 4;           // 0..1 -> rows hq*4..hq*4+3
    const int cg = t >> 5;           // 0..3 cout group (8 pairs each)

    const float* srcI = nullptr;
    const float2* Wt2;
    if (MODE == 0) {
        if (isNbr) {
            const float* mp = g_mask + (long)img * NPIX;
            int any = (mp[(h0 + (t >> 4)) * HW + (w0 + (t & 15))] != 0.0f);
            if (__syncthreads_count(any) == 0) return;
            int b = img >> 4, i = (img >> 2) & 3;
            srcI = ysrc + (long)(b * 4 + i) * 64 * NPIX;
            const float* mv = g_minv + img * 6;
            for (int idx = t; idx < 180; idx += 128) {
                int r = idx / 18, c = idx % 18;
                int gh = h0 - 1 + r, gw = w0 - 1 + c;
                float4 wv = make_float4(0.f, 0.f, 0.f, 0.f);
                int4 iv = make_int4(0, 0, 0, 0);
                if (gh >= 0 && gh < HW && gw >= 0 && gw < HW) {
                    float X = (float)gw, Y = (float)gh;
                    float sx = coordx(mv, X, Y);
                    float sy = coordy(mv, X, Y);
                    float x0f = floorf(sx), y0f = floorf(sy);
                    float fx = __fsub_rn(sx, x0f), fy = __fsub_rn(sy, y0f);
                    int x0 = (int)x0f, y0 = (int)y0f;
                    int x1 = x0 + 1, y1 = y0 + 1;
                    int cx0 = min(max(x0, 0), HW - 1), cx1 = min(max(x1, 0), HW - 1);
                    int cy0 = min(max(y0, 0), HW - 1), cy1 = min(max(y1, 0), HW - 1);
                    float vx0 = (x0 >= 0 && x0 < HW) ? 1.0f : 0.0f;
                    float vx1 = (x1 >= 0 && x1 < HW) ? 1.0f : 0.0f;
                    float vy0 = (y0 >= 0 && y0 < HW) ? 1.0f : 0.0f;
                    float vy1 = (y1 >= 0 && y1 < HW) ? 1.0f : 0.0f;
                    float gx = __fsub_rn(1.0f, fx), gy = __fsub_rn(1.0f, fy);
                    wv.x = __fmul_rn(__fmul_rn(vx0, vy0), __fmul_rn(gx, gy));
                    wv.y = __fmul_rn(__fmul_rn(vx1, vy0), __fmul_rn(fx, gy));
                    wv.z = __fmul_rn(__fmul_rn(vx0, vy1), __fmul_rn(gx, fy));
                    wv.w = __fmul_rn(__fmul_rn(vx1, vy1), __fmul_rn(fx, fy));
                    iv.x = cy0 * HW + cx0; iv.y = cy0 * HW + cx1;
                    iv.z = cy1 * HW + cx0; iv.w = cy1 * HW + cx1;
                }
                aux.nbr.w[idx] = wv;
                aux.nbr.iv[idx] = iv;
            }
            __syncthreads();
            Wt2 = Wnbr;
        } else {
            srcI = ysrc + (long)img * 64 * NPIX;
            Wt2 = Wego;
        }
    } else {
        srcI = ysrc + (long)img * 64 * NPIX;
        Wt2 = Wnbr;                  // carries gru weights in MODE2 call
        int b = img >> 2, j = img & 3;
        for (int idx = t; idx < 180; idx += 128) {
            int r = idx / 18, c = idx % 18;
            int gh = h0 - 1 + r, gw = w0 - 1 + c;
            float ms = 0.f, m0 = 0.f, m1 = 0.f, m2 = 0.f, m3 = 0.f;
            if (gh >= 0 && gh < HW && gw >= 0 && gw < HW) {
                int p = gh * HW + gw;
                ms = g_masksum[img * NPIX + p];
                m0 = g_mask[((b * 4 + 0) * 4 + j) * NPIX + p];
                m1 = g_mask[((b * 4 + 1) * 4 + j) * NPIX + p];
                m2 = g_mask[((b * 4 + 2) * 4 + j) * NPIX + p];
                m3 = g_mask[((b * 4 + 3) * 4 + j) * NPIX + p];
            }
            aux.gru.mk[idx][0] = ms; aux.gru.mk[idx][1] = m0;
            aux.gru.mk[idx][2] = m1; aux.gru.mk[idx][3] = m2;
            aux.gru.mk[idx][4] = m3;
        }
        __syncthreads();
    }

    ull acc2[4][8];
#pragma unroll
    for (int k = 0; k < 4; k++)
#pragma unroll
        for (int j = 0; j < 8; j++) acc2[k][j] = 0ULL;

    for (int cin0 = 0; cin0 < CIN; cin0 += 8) {
        // ---- stage input: 8ci x 10 x 18 ----
        for (int idx = t; idx < 8 * 180; idx += 128) {
            int ci = idx / 180, rem = idx % 180;
            int r = rem / 18, c = rem % 18;
            float v = 0.0f;
            if (MODE == 0 && isNbr) {
                float4 wv = aux.nbr.w[rem];
                int4 iv = aux.nbr.iv[rem];
                const float* sc = srcI + (cin0 + ci) * NPIX;
                v = __fmul_rn(wv.x, sc[iv.x]);
                v = __fadd_rn(v, __fmul_rn(wv.y, sc[iv.y]));
                v = __fadd_rn(v, __fmul_rn(wv.z, sc[iv.z]));
                v = __fadd_rn(v, __fmul_rn(wv.w, sc[iv.w]));
            } else {
                int gh = h0 - 1 + r, gw = w0 - 1 + c;
                if (gh >= 0 && gh < HW && gw >= 0 && gw < HW) {
                    int p = gh * HW + gw;
                    if (MODE == 0 || cin0 < 64) {
                        v = srcI[(cin0 + ci) * NPIX + p];
                    } else {
                        int cb = cin0 - 64 + ci;
                        int b = img >> 2, j = img & 3;
                        v = __fmul_rn(aux.gru.mk[rem][0],
                                      ego[((long)img * 64 + cb) * NPIX + p]);
                        v = __fmaf_rn(aux.gru.mk[rem][1],
                                      convn[((long)((b * 4 + 0) * 4 + j) * 64 + cb) * NPIX + p], v);
                        v = __fmaf_rn(aux.gru.mk[rem][2],
                                      convn[((long)((b * 4 + 1) * 4 + j) * 64 + cb) * NPIX + p], v);
                        v = __fmaf_rn(aux.gru.mk[rem][3],
                                      convn[((long)((b * 4 + 2) * 4 + j) * 64 + cb) * NPIX + p], v);
                        v = __fmaf_rn(aux.gru.mk[rem][4],
                                      convn[((long)((b * 4 + 3) * 4 + j) * 64 + cb) * NPIX + p], v);
                        v = __fmul_rn(0.25f, v);
                    }
                }
            }
            sX[ci][r][c] = v;
        }
        // ---- stage weights: 32 pairs x 8ci x 9 (float2) ----
        for (int idx = t; idx < 32 * 72; idx += 128) {
            int co2 = idx / 72, rem = idx % 72;
            sW2[co2 * 72 + rem] =
                Wt2[((blockIdx.y * 32 + co2) * CIN + cin0) * 9 + rem];
        }
        __syncthreads();
#pragma unroll 1
        for (int ci = 0; ci < 8; ci++) {
            ull xb[6][3];
#pragma unroll
            for (int rr = 0; rr < 6; rr++)
#pragma unroll
                for (int cc = 0; cc < 3; cc++)
                    xb[rr][cc] = bcast2(sX[ci][hq * 4 + rr][wl + cc]);
            const float2* wp = &sW2[(cg * 8) * 72 + ci * 9];
#pragma unroll
            for (int j = 0; j < 8; j++) {
#pragma unroll
                for (int tap = 0; tap < 9; tap++) {
                    ull w2 = *reinterpret_cast<const ull*>(&wp[j * 72 + tap]);
                    int r = tap / 3, c = tap % 3;
                    fma2(acc2[0][j], xb[0 + r][c], w2);
                    fma2(acc2[1][j], xb[1 + r][c], w2);
                    fma2(acc2[2][j], xb[2 + r][c], w2);
                    fma2(acc2[3][j], xb[3 + r][c], w2);
                }
            }
        }
        __syncthreads();
    }
    // ---- epilogue ----
    if (MODE == 2) {
#pragma unroll
        for (int j = 0; j < 8; j++) {
            int pr = blockIdx.y * 32 + cg * 8 + j;
            float2 bb = bgru2[pr];
#pragma unroll
            for (int k = 0; k < 4; k++) {
                int h = h0 + hq * 4 + k, w = w0 + wl;
                float2 f = unpack2(acc2[k][j]);
                ydst[((long)img * 64 + pr) * NPIX + h * HW + w] =
                    sigmoid_acc(f.x + bb.x) * tanh_acc(f.y + bb.y);
            }
        }
    } else {
        float* outp = isNbr ? (convn_out + (long)img * 64 * NPIX)
                            : (ego_out + (long)img * 64 * NPIX);
#pragma unroll
        for (int j = 0; j < 8; j++) {
            int co = (cg * 8 + j) * 2;
            float bv0 = isNbr ? 0.0f : msgb[co];
            float bv1 = isNbr ? 0.0f : msgb[co + 1];
#pragma unroll
            for (int k = 0; k < 4; k++) {
                int h = h0 + hq * 4 + k, w = w0 + wl;
                float2 f = unpack2(acc2[k][j]);
                outp[(long)co * NPIX + h * HW + w] = f.x + bv0;
                outp[(long)(co + 1) * NPIX + h * HW + w] = f.y + bv1;
            }
        }
    }
}

// ---------------- weight prepack ----------------
__global__ void k_prepack(const float* __restrict__ msg_w,
                          const float* __restrict__ gates_w,
                          const float* __restrict__ gates_b,
                          const float* __restrict__ can_w,
                          const float* __restrict__ can_b) {
    int idx = blockIdx.x * 256 + threadIdx.x;
    if (idx < 18432) {                         // msg split: [co2][ci<64][9]
        int co2 = idx / 576, rem = idx % 576;
        int coA = 2 * co2, coB = 2 * co2 + 1;
        g_wnbr2[idx] = make_float2(msg_w[coA * 1152 + rem],
                                   msg_w[coB * 1152 + rem]);
        g_wego2[idx] = make_float2(msg_w[coA * 1152 + 576 + rem],
                                   msg_w[coB * 1152 + 576 + rem]);
        return;
    }
    int k = idx - 18432;
    if (k < 73728) {                           // gru (update,cand) lane pairs
        int pr = k / 1152, rem = k % 1152;
        g_wgru2[k] = make_float2(gates_w[(64 + pr) * 1728 + rem],
                                 can_w[pr * 1728 + rem]);
        return;
    }
    k -= 73728;
    if (k < 64)
        g_bgru2[k] = make_float2(gates_b[64 + k], can_b[k]);
}

// ---------------- output: out[b,h,w,o] = mlp_w[o,:]·h1[b,0,:,w,79-h]+mlp_b ----
__global__ void k_out(const float* __restrict__ mlp_w,
                      const float* __restrict__ mlp_b,
                      const float* __restrict__ yfin,
                      float* __restrict__ out) {
    __shared__ float sW[64 * 65];
    __shared__ float sx[4][64];
    int t = threadIdx.x;
    for (int idx = t; idx < 4096; idx += 256) {
        int o = idx >> 6, c = idx & 63;
        sW[c * 65 + o] = mlp_w[idx];
    }
    int pix = t >> 6, o = t & 63;
    int pp = blockIdx.x * 4 + pix;
    int b = pp / NPIX, pr = pp % NPIX;
    int h = pr / HW, w = pr % HW;
    int q = w * HW + (HW - 1 - h);
    sx[pix][o] = yfin[(b * 4) * 64 * NPIX + o * NPIX + q];
    __syncthreads();
    float acc = mlp_b[o];
#pragma unroll 8
    for (int c = 0; c < 64; c++)
        acc = fmaf(sx[pix][c], sW[c * 65 + o], acc);
    out[pp * 64 + o] = acc;
}

// ---------------- host orchestration ----------------
extern "C" void kernel_launch(void* const* d_in, const int* in_sizes, int n_in,
                              void* d_out, int out_size) {
    const float* x       = (const float*)d_in[0];
    const float* pt      = (const float*)d_in[2];
    const float* msg_w   = (const float*)d_in[4];
    const float* msg_b   = (const float*)d_in[5];
    const float* gates_w = (const float*)d_in[6];
    const float* gates_b = (const float*)d_in[7];
    const float* can_w   = (const float*)d_in[8];
    const float* can_b   = (const float*)d_in[9];
    const float* mlp_w   = (const float*)d_in[10];
    const float* mlp_b   = (const float*)d_in[11];

    float *p_y, *p_y2, *p_convn, *p_ego;
    float2 *p_wnbr2, *p_wego2, *p_wgru2, *p_bgru2;
    cudaGetSymbolAddress((void**)&p_y, g_y);
    cudaGetSymbolAddress((void**)&p_y2, g_y2);
    cudaGetSymbolAddress((void**)&p_convn, g_convn);
    cudaGetSymbolAddress((void**)&p_ego, g_ego);
    cudaGetSymbolAddress((void**)&p_wnbr2, g_wnbr2);
    cudaGetSymbolAddress((void**)&p_wego2, g_wego2);
    cudaGetSymbolAddress((void**)&p_wgru2, g_wgru2);
    cudaGetSymbolAddress((void**)&p_bgru2, g_bgru2);

    k_minv<<<1, 32>>>(pt);
    k_prepack<<<(18432 + 73728 + 64 + 255) / 256, 256>>>(msg_w, gates_w,
                                                         gates_b, can_w, can_b);
    k_maskall<<<dim3(25, NIMG), 256>>>();
    k_transform<<<(NIMG * 64 * NPIX) / 256, 256>>>(x);

    for (int it = 0; it < 2; it++) {
        const float* ysrc = (it == 0) ? p_y : p_y2;
        float* ydst       = (it == 0) ? p_y2 : p_y;
        // merged NBR(32 pairs) + EGO(8 imgs): 2000 blocks of 128 thr
        conv_all<0, 64><<<dim3(50, 1, 40), 128>>>(
            ysrc, nullptr, nullptr, p_wnbr2, p_wego2, msg_b, nullptr,
            p_convn, p_ego, nullptr);
        // GRU conv with fused agg + pointwise: 800 blocks of 128 thr
        conv_all<2, 128><<<dim3(50, 2, NIMG), 128>>>(
            ysrc, p_convn, p_ego, p_wgru2, nullptr, nullptr, p_bgru2,
            nullptr, nullptr, ydst);
    }

    k_out<<<2 * NPIX / 4, 256>>>(mlp_w, mlp_b, p_y, (float*)d_out);
}